// round 12
// baseline (speedup 1.0000x reference)
#include <cuda_runtime.h>
#include <cuda_bf16.h>
#include <mma.h>

using namespace nvcuda;

#define SQ 4096
#define HD 256
#define NHEAD 6
#define H3 768

// ---------------- scratch (static __device__ — no allocation) ----------------
__device__ float g_x[SQ * HD];                            // embedded tokens
__device__ __nv_bfloat16 g_qb[NHEAD * SQ * HD];           // q (bf16)
__device__ __nv_bfloat16 g_kb[NHEAD * SQ * HD];           // k (bf16)
__device__ __nv_bfloat16 g_vb[NHEAD * SQ * HD];           // v (bf16)
__device__ float g_scores[(size_t)NHEAD * SQ * SQ];       // raw scores fp32
__device__ __nv_bfloat16 g_pb[(size_t)NHEAD * SQ * SQ];   // softmax(P) bf16
__device__ float g_ocat[SQ * NHEAD * HD];                 // concat [s][h*H+e]
__device__ float g_yo[SQ * HD];                           // attn projection out
__device__ float g_y[SQ * HD];                            // post-LN
__device__ float g_gi[SQ * H3];                           // y @ W_ih^T + b_ih

// ---------------- packed f32x2 helpers ----------------
__device__ __forceinline__ unsigned long long pack2f(float x) {
    unsigned long long r;
    asm("mov.b64 %0, {%1, %1};" : "=l"(r) : "f"(x));
    return r;
}
__device__ __forceinline__ unsigned long long pack2(float lo, float hi) {
    unsigned long long r;
    asm("mov.b64 %0, {%1, %2};" : "=l"(r) : "f"(lo), "f"(hi));
    return r;
}
__device__ __forceinline__ void unpack2(unsigned long long v, float& lo, float& hi) {
    asm("mov.b64 {%0, %1}, %2;" : "=f"(lo), "=f"(hi) : "l"(v));
}
__device__ __forceinline__ void ffma2(unsigned long long& d,
                                      unsigned long long a,
                                      unsigned long long b) {
    asm("fma.rn.f32x2 %0, %1, %2, %3;" : "=l"(d) : "l"(a), "l"(b), "l"(d));
}
__device__ __forceinline__ unsigned smem_u32(const void* p) {
    unsigned r;
    asm("{ .reg .u64 t; cvta.to.shared.u64 t, %1; cvt.u32.u64 %0, t; }"
        : "=r"(r) : "l"(p));
    return r;
}
__device__ __forceinline__ unsigned mapa_rank(unsigned addr, unsigned rank) {
    unsigned r;
    asm("mapa.shared::cluster.u32 %0, %1, %2;" : "=r"(r) : "r"(addr), "r"(rank));
    return r;
}
__device__ __forceinline__ void st_cluster_f32(unsigned addr, float v) {
    asm volatile("st.shared::cluster.f32 [%0], %1;" :: "r"(addr), "f"(v) : "memory");
}
__device__ __forceinline__ void st_rel_cluster_u32(unsigned addr, unsigned v) {
    asm volatile("st.release.cluster.shared::cluster.u32 [%0], %1;"
                 :: "r"(addr), "r"(v) : "memory");
}
__device__ __forceinline__ unsigned long long ld_acq_u64(unsigned addr) {
    unsigned long long v;
    asm volatile("ld.acquire.cluster.shared::cta.b64 %0, [%1];"
                 : "=l"(v) : "r"(addr) : "memory");
    return v;
}
__device__ __forceinline__ unsigned my_ctarank() {
    unsigned r;
    asm("mov.u32 %0, %%cluster_ctarank;" : "=r"(r));
    return r;
}

// ---------------- embedding gather ----------------
__global__ void embed_kernel(const int* __restrict__ tok,
                             const float* __restrict__ emb) {
    int s = blockIdx.x, t = threadIdx.x;
    g_x[s * HD + t] = emb[(long long)tok[s] * HD + t];
}

// ---------------- fp32 SGEMM (f32x2 packed), optional bf16 output -----------
template <bool TRANSB, bool HASBIAS, bool OUTBF16>
__global__ __launch_bounds__(256, 2)
void sgemm_kernel(int M, int N, int K,
                  const float* __restrict__ A, int lda, long long sA,
                  const float* __restrict__ B, int ldb, long long sB,
                  const float* __restrict__ bias, int sBias,
                  void* __restrict__ Cv, int ldc, long long sC,
                  float alpha) {
    __shared__ float As[2][16][132];
    __shared__ float Bs[2][16][132];

    int z = blockIdx.z;
    A += (long long)z * sA;
    B += (long long)z * sB;
    const float* bp = HASBIAS ? (bias + (long long)z * sBias) : nullptr;

    int tid = threadIdx.x;
    int tx = tid & 15, ty = tid >> 4;
    int brow = blockIdx.y * 128, bcol = blockIdx.x * 128;

    int lrow = tid >> 1;
    int lcb  = (tid & 1) * 8;
    int bkr  = tid >> 4;
    int bcb  = (tid & 15) * 8;

    unsigned long long acc[8][4];
#pragma unroll
    for (int i = 0; i < 8; i++)
#pragma unroll
        for (int j = 0; j < 4; j++) acc[i][j] = 0ull;

    float4 na0, na1, nb0, nb1;

    auto LOADG = [&](int k0) {
        const float* ap = A + (long long)(brow + lrow) * lda + k0 + lcb;
        na0 = *(const float4*)ap;
        na1 = *(const float4*)(ap + 4);
        if (TRANSB) {
            const float* bpt = B + (long long)(bcol + lrow) * ldb + k0 + lcb;
            nb0 = *(const float4*)bpt;
            nb1 = *(const float4*)(bpt + 4);
        } else {
            const float* bpt = B + (long long)(k0 + bkr) * ldb + bcol + bcb;
            nb0 = *(const float4*)bpt;
            nb1 = *(const float4*)(bpt + 4);
        }
    };
    auto STORES = [&](int buf) {
        As[buf][lcb + 0][lrow] = na0.x; As[buf][lcb + 1][lrow] = na0.y;
        As[buf][lcb + 2][lrow] = na0.z; As[buf][lcb + 3][lrow] = na0.w;
        As[buf][lcb + 4][lrow] = na1.x; As[buf][lcb + 5][lrow] = na1.y;
        As[buf][lcb + 6][lrow] = na1.z; As[buf][lcb + 7][lrow] = na1.w;
        if (TRANSB) {
            Bs[buf][lcb + 0][lrow] = nb0.x; Bs[buf][lcb + 1][lrow] = nb0.y;
            Bs[buf][lcb + 2][lrow] = nb0.z; Bs[buf][lcb + 3][lrow] = nb0.w;
            Bs[buf][lcb + 4][lrow] = nb1.x; Bs[buf][lcb + 5][lrow] = nb1.y;
            Bs[buf][lcb + 6][lrow] = nb1.z; Bs[buf][lcb + 7][lrow] = nb1.w;
        } else {
            *(float4*)&Bs[buf][bkr][bcb]     = nb0;
            *(float4*)&Bs[buf][bkr][bcb + 4] = nb1;
        }
    };

    LOADG(0);
    STORES(0);
    __syncthreads();

    int buf = 0;
    for (int k0 = 0; k0 < K; k0 += 16) {
        bool has_next = (k0 + 16) < K;
        if (has_next) LOADG(k0 + 16);
#pragma unroll
        for (int kk = 0; kk < 16; kk++) {
            float av[8];
            *(float4*)&av[0] = *(const float4*)&As[buf][kk][ty * 8];
            *(float4*)&av[4] = *(const float4*)&As[buf][kk][ty * 8 + 4];
            unsigned long long bq[4];
            bq[0] = *(const unsigned long long*)&Bs[buf][kk][tx * 8];
            bq[1] = *(const unsigned long long*)&Bs[buf][kk][tx * 8 + 2];
            bq[2] = *(const unsigned long long*)&Bs[buf][kk][tx * 8 + 4];
            bq[3] = *(const unsigned long long*)&Bs[buf][kk][tx * 8 + 6];
#pragma unroll
            for (int i = 0; i < 8; i++) {
                unsigned long long apk = pack2f(av[i]);
                ffma2(acc[i][0], apk, bq[0]);
                ffma2(acc[i][1], apk, bq[1]);
                ffma2(acc[i][2], apk, bq[2]);
                ffma2(acc[i][3], apk, bq[3]);
            }
        }
        if (has_next) {
            STORES(buf ^ 1);
            __syncthreads();
            buf ^= 1;
        }
    }

    float bb[8];
    if (HASBIAS) {
        *(float4*)&bb[0] = *(const float4*)&bp[bcol + tx * 8];
        *(float4*)&bb[4] = *(const float4*)&bp[bcol + tx * 8 + 4];
    }
#pragma unroll
    for (int i = 0; i < 8; i++) {
        long long row = brow + ty * 8 + i;
        float2 p0, p1, p2, p3;
        unpack2(acc[i][0], p0.x, p0.y);
        unpack2(acc[i][1], p1.x, p1.y);
        unpack2(acc[i][2], p2.x, p2.y);
        unpack2(acc[i][3], p3.x, p3.y);
        float4 o0, o1;
        o0.x = p0.x * alpha; o0.y = p0.y * alpha;
        o0.z = p1.x * alpha; o0.w = p1.y * alpha;
        o1.x = p2.x * alpha; o1.y = p2.y * alpha;
        o1.z = p3.x * alpha; o1.w = p3.y * alpha;
        if (HASBIAS) {
            o0.x += bb[0]; o0.y += bb[1]; o0.z += bb[2]; o0.w += bb[3];
            o1.x += bb[4]; o1.y += bb[5]; o1.z += bb[6]; o1.w += bb[7];
        }
        long long coff = row * (long long)ldc + bcol + tx * 8 + (long long)z * sC;
        if (OUTBF16) {
            __nv_bfloat16* cb = (__nv_bfloat16*)Cv + coff;
            __nv_bfloat162 hb[4];
            hb[0] = __floats2bfloat162_rn(o0.x, o0.y);
            hb[1] = __floats2bfloat162_rn(o0.z, o0.w);
            hb[2] = __floats2bfloat162_rn(o1.x, o1.y);
            hb[3] = __floats2bfloat162_rn(o1.z, o1.w);
            *(uint4*)cb = *(uint4*)hb;
        } else {
            float* cr = (float*)Cv + coff;
            *(float4*)cr = o0;
            *(float4*)(cr + 4) = o1;
        }
    }
}

// ---------------- bf16 wmma GEMM: C(fp32) = A(bf16) * B(^T)(bf16) -----------
template <bool TRANSB>
__global__ __launch_bounds__(256, 2)
void bf16gemm_kernel(int M, int N, int K,
                     const __nv_bfloat16* __restrict__ A, int lda, long long sA,
                     const __nv_bfloat16* __restrict__ B, int ldb, long long sB,
                     float* __restrict__ C, int ldc, long long sC) {
    __shared__ __align__(16) __nv_bfloat16 As[128][40];
    __shared__ __align__(16) __nv_bfloat16 Bsh[128 * 40];   // NT: [n][40]; NN: [32][136]

    int z = blockIdx.z;
    A += (long long)z * sA;
    B += (long long)z * sB;
    C += (long long)z * sC;

    int tid = threadIdx.x;
    int wid = tid >> 5;
    int warp_m = wid & 3;
    int warp_n = wid >> 2;
    int brow = blockIdx.y * 128, bcol = blockIdx.x * 128;

    wmma::fragment<wmma::accumulator, 16, 16, 16, float> acc[2][4];
#pragma unroll
    for (int mi = 0; mi < 2; mi++)
#pragma unroll
        for (int ni = 0; ni < 4; ni++) wmma::fill_fragment(acc[mi][ni], 0.0f);

    for (int k0 = 0; k0 < K; k0 += 32) {
#pragma unroll
        for (int j = 0; j < 2; j++) {
            int u = tid + 256 * j;
            int row = u >> 2, col = (u & 3) * 8;
            const __nv_bfloat16* src = A + (long long)(brow + row) * lda + k0 + col;
            *(uint4*)&As[row][col] = *(const uint4*)src;
        }
        if (TRANSB) {
#pragma unroll
            for (int j = 0; j < 2; j++) {
                int u = tid + 256 * j;
                int row = u >> 2, col = (u & 3) * 8;
                const __nv_bfloat16* src = B + (long long)(bcol + row) * ldb + k0 + col;
                *(uint4*)&Bsh[row * 40 + col] = *(const uint4*)src;
            }
        } else {
#pragma unroll
            for (int j = 0; j < 2; j++) {
                int u = tid + 256 * j;
                int row = u >> 4, col = (u & 15) * 8;
                const __nv_bfloat16* src = B + (long long)(k0 + row) * ldb + bcol + col;
                *(uint4*)&Bsh[row * 136 + col] = *(const uint4*)src;
            }
        }
        __syncthreads();

#pragma unroll
        for (int ks = 0; ks < 2; ks++) {
            int kk = ks * 16;
            wmma::fragment<wmma::matrix_a, 16, 16, 16, __nv_bfloat16, wmma::row_major> af[2];
#pragma unroll
            for (int mi = 0; mi < 2; mi++)
                wmma::load_matrix_sync(af[mi], &As[warp_m * 32 + mi * 16][kk], 40);
            if (TRANSB) {
                wmma::fragment<wmma::matrix_b, 16, 16, 16, __nv_bfloat16, wmma::col_major> bf[4];
#pragma unroll
                for (int ni = 0; ni < 4; ni++)
                    wmma::load_matrix_sync(bf[ni], &Bsh[(warp_n * 64 + ni * 16) * 40 + kk], 40);
#pragma unroll
                for (int mi = 0; mi < 2; mi++)
#pragma unroll
                    for (int ni = 0; ni < 4; ni++)
                        wmma::mma_sync(acc[mi][ni], af[mi], bf[ni], acc[mi][ni]);
            } else {
                wmma::fragment<wmma::matrix_b, 16, 16, 16, __nv_bfloat16, wmma::row_major> bf[4];
#pragma unroll
                for (int ni = 0; ni < 4; ni++)
                    wmma::load_matrix_sync(bf[ni], &Bsh[kk * 136 + warp_n * 64 + ni * 16], 136);
#pragma unroll
                for (int mi = 0; mi < 2; mi++)
#pragma unroll
                    for (int ni = 0; ni < 4; ni++)
                        wmma::mma_sync(acc[mi][ni], af[mi], bf[ni], acc[mi][ni]);
            }
        }
        __syncthreads();
    }

#pragma unroll
    for (int mi = 0; mi < 2; mi++)
#pragma unroll
        for (int ni = 0; ni < 4; ni++) {
            long long row = brow + warp_m * 32 + mi * 16;
            long long col = bcol + warp_n * 64 + ni * 16;
            wmma::store_matrix_sync(C + row * ldc + col, acc[mi][ni], ldc,
                                    wmma::mem_row_major);
        }
}

// ---------------- row softmax (fp32 in, bf16 out), 1/16 scale folded --------
__global__ __launch_bounds__(256) void softmax_kernel(const float* __restrict__ P,
                                                      __nv_bfloat16* __restrict__ Pb) {
    __shared__ float sm[8];
    __shared__ float bc;
    long long base = (long long)blockIdx.x * SQ;
    const float4* p4 = (const float4*)(P + base);
    __nv_bfloat162* ob = (__nv_bfloat162*)(Pb + base);
    int tid = threadIdx.x;

    float4 v[4];
#pragma unroll
    for (int i = 0; i < 4; i++) v[i] = p4[tid + 256 * i];

    float m = -1e30f;
#pragma unroll
    for (int i = 0; i < 4; i++)
        m = fmaxf(m, fmaxf(fmaxf(v[i].x, v[i].y), fmaxf(v[i].z, v[i].w)));
#pragma unroll
    for (int off = 16; off; off >>= 1)
        m = fmaxf(m, __shfl_xor_sync(0xffffffffu, m, off));
    if ((tid & 31) == 0) sm[tid >> 5] = m;
    __syncthreads();
    if (tid == 0) {
        float t = sm[0];
#pragma unroll
        for (int j = 1; j < 8; j++) t = fmaxf(t, sm[j]);
        bc = t;
    }
    __syncthreads();
    m = bc;

    float s = 0.f;
#pragma unroll
    for (int i = 0; i < 4; i++) {
        v[i].x = __expf((v[i].x - m) * 0.0625f);
        v[i].y = __expf((v[i].y - m) * 0.0625f);
        v[i].z = __expf((v[i].z - m) * 0.0625f);
        v[i].w = __expf((v[i].w - m) * 0.0625f);
        s += v[i].x + v[i].y + v[i].z + v[i].w;
    }
#pragma unroll
    for (int off = 16; off; off >>= 1)
        s += __shfl_xor_sync(0xffffffffu, s, off);
    __syncthreads();
    if ((tid & 31) == 0) sm[tid >> 5] = s;
    __syncthreads();
    if (tid == 0) {
        float t = 0.f;
#pragma unroll
        for (int j = 0; j < 8; j++) t += sm[j];
        bc = 1.0f / t;
    }
    __syncthreads();
    float inv = bc;
#pragma unroll
    for (int i = 0; i < 4; i++) {
        int idx = tid + 256 * i;
        ob[idx * 2 + 0] = __floats2bfloat162_rn(v[i].x * inv, v[i].y * inv);
        ob[idx * 2 + 1] = __floats2bfloat162_rn(v[i].z * inv, v[i].w * inv);
    }
}

// ---------------- residual + LayerNorm ----------------
__global__ __launch_bounds__(256) void addln_kernel(const float* __restrict__ lng,
                                                    const float* __restrict__ lnb) {
    __shared__ float sm[8];
    __shared__ float bc;
    int s = blockIdx.x, t = threadIdx.x;
    float v = g_x[s * HD + t] + g_yo[s * HD + t];

    float a = v;
#pragma unroll
    for (int off = 16; off; off >>= 1) a += __shfl_xor_sync(0xffffffffu, a, off);
    if ((t & 31) == 0) sm[t >> 5] = a;
    __syncthreads();
    if (t == 0) {
        float tt = 0.f;
#pragma unroll
        for (int j = 0; j < 8; j++) tt += sm[j];
        bc = tt * (1.0f / HD);
    }
    __syncthreads();
    float mu = bc;
    float d = v - mu;
    float q = d * d;
    __syncthreads();
#pragma unroll
    for (int off = 16; off; off >>= 1) q += __shfl_xor_sync(0xffffffffu, q, off);
    if ((t & 31) == 0) sm[t >> 5] = q;
    __syncthreads();
    if (t == 0) {
        float tt = 0.f;
#pragma unroll
        for (int j = 0; j < 8; j++) tt += sm[j];
        bc = tt * (1.0f / HD);
    }
    __syncthreads();
    float var = bc;
    g_y[s * HD + t] = d * rsqrtf(var + 1e-5f) * lng[t] + lnb[t];
}

// ---------------- cluster GRU scan (LSU flag-poll handshake) -----------------
// 8-CTA cluster, 1024 threads each. CTA rank b owns hidden [b*32, b*32+32);
// warp w computes i = b*32 + w with 8 elems/lane of W_hh in registers.
// Per step: lanes 0..7 store h2 directly into all 8 CTAs' hs[nxt] (DSMEM);
// __syncthreads; threads 0..7 fence + st.release step-number t into peer
// tid's flags[nxt][rank]; all threads spin on LOCAL flags with acquire
// loads until all 8 == t. No SYNCS-unit primitives in the steady state.
__global__ void __cluster_dims__(8, 1, 1) __launch_bounds__(1024, 1)
gru_cluster_kernel(const float* __restrict__ gi,
                   const float* __restrict__ Whh,
                   const float* __restrict__ bhh,
                   float* __restrict__ out, int out_n) {
    __shared__ float hs[2][HD];
    __shared__ __align__(16) int flags[2][8];

    int tid = threadIdx.x;
    int w = tid >> 5, l = tid & 31;
    unsigned rank = my_ctarank();
    int i = (int)rank * 32 + w;

    // register-resident, pair-packed W_hh slices
    unsigned long long wrp[4], wzp[4], wnp[4];
    {
        const float4* r4 = (const float4*)(Whh + (long long)i * HD + l * 8);
        float4 t0 = r4[0], t1 = r4[1];
        wrp[0] = pack2(t0.x, t0.y); wrp[1] = pack2(t0.z, t0.w);
        wrp[2] = pack2(t1.x, t1.y); wrp[3] = pack2(t1.z, t1.w);
        const float4* z4 = (const float4*)(Whh + (long long)(HD + i) * HD + l * 8);
        t0 = z4[0]; t1 = z4[1];
        wzp[0] = pack2(t0.x, t0.y); wzp[1] = pack2(t0.z, t0.w);
        wzp[2] = pack2(t1.x, t1.y); wzp[3] = pack2(t1.z, t1.w);
        const float4* n4 = (const float4*)(Whh + (long long)(2 * HD + i) * HD + l * 8);
        t0 = n4[0]; t1 = n4[1];
        wnp[0] = pack2(t0.x, t0.y); wnp[1] = pack2(t0.z, t0.w);
        wnp[2] = pack2(t1.x, t1.y); wnp[3] = pack2(t1.z, t1.w);
    }
    float br = 0.f, bz = 0.f, bn = 0.f;
    if (l == 0) { br = bhh[i]; bz = bhh[HD + i]; bn = bhh[2 * HD + i]; }

    unsigned hb = smem_u32(&hs[0][0]);
    unsigned fb = smem_u32(&flags[0][0]);

    // remote h-store addresses for this warp's slot (lanes 0..7 -> rank l)
    unsigned ra0 = 0, ra1 = 0;
    if (l < 8) {
        ra0 = mapa_rank(hb + (unsigned)i * 4u, (unsigned)l);
        ra1 = mapa_rank(hb + (unsigned)(HD + i) * 4u, (unsigned)l);
    }
    // remote flag addresses (threads 0..7 -> dest rank tid, slot = my rank)
    unsigned rf0 = 0, rf1 = 0;
    if (tid < 8) {
        rf0 = mapa_rank(fb + rank * 4u, (unsigned)tid);
        rf1 = mapa_rank(fb + 32u + rank * 4u, (unsigned)tid);
    }

    if (tid < HD) { hs[0][tid] = 0.0f; hs[1][tid] = 0.0f; }
    if (tid < 16) ((int*)flags)[tid] = -1;
    __syncthreads();
    // zeroed hs/flags visible cluster-wide before any remote stores
    asm volatile("barrier.cluster.arrive.aligned;" ::: "memory");
    asm volatile("barrier.cluster.wait.aligned;" ::: "memory");

    const float* gp = gi + i;
    float gir = 0.f, giz = 0.f, gin = 0.f;
    if (l == 0) { gir = __ldg(gp); giz = __ldg(gp + HD); gin = __ldg(gp + 2 * HD); }
    gp += H3;

    for (int t = 0; t < SQ; t++) {
        int cur = t & 1;
        int nxt = cur ^ 1;
        const unsigned long long* hq = (const unsigned long long*)&hs[cur][l * 8];
        unsigned long long h0 = hq[0], h1 = hq[1], h2p = hq[2], h3 = hq[3];
        unsigned long long ar = 0ull, az = 0ull, an = 0ull;
        ffma2(ar, wrp[0], h0); ffma2(az, wzp[0], h0); ffma2(an, wnp[0], h0);
        ffma2(ar, wrp[1], h1); ffma2(az, wzp[1], h1); ffma2(an, wnp[1], h1);
        ffma2(ar, wrp[2], h2p); ffma2(az, wzp[2], h2p); ffma2(an, wnp[2], h2p);
        ffma2(ar, wrp[3], h3); ffma2(az, wzp[3], h3); ffma2(an, wnp[3], h3);
        float drl, drh, dzl, dzh, dnl, dnh;
        unpack2(ar, drl, drh);
        unpack2(az, dzl, dzh);
        unpack2(an, dnl, dnh);
        float dr = drl + drh, dz = dzl + dzh, dn = dnl + dnh;
#pragma unroll
        for (int off = 16; off; off >>= 1) {
            dr += __shfl_xor_sync(0xffffffffu, dr, off);
            dz += __shfl_xor_sync(0xffffffffu, dz, off);
            dn += __shfl_xor_sync(0xffffffffu, dn, off);
        }
        float h2 = 0.f;
        if (l == 0) {
            float hprev = hs[cur][i];
            float r = 1.0f / (1.0f + __expf(-(gir + br + dr)));
            float z = 1.0f / (1.0f + __expf(-(giz + bz + dz)));
            float n = tanhf(gin + r * (dn + bn));
            h2 = (1.0f - z) * n + z * hprev;
        }
        h2 = __shfl_sync(0xffffffffu, h2, 0);
        // prefetch next step's gi (hides under fan-out + poll)
        if (l == 0 && t + 1 < SQ) {
            gir = __ldg(gp); giz = __ldg(gp + HD); gin = __ldg(gp + 2 * HD);
            gp += H3;
        }
        if (l < 8) {
            st_cluster_f32(nxt ? ra1 : ra0, h2);
        }
        __syncthreads();                   // intra-CTA hb: all h stores issued
        if (tid < 8) {
            asm volatile("fence.acq_rel.cluster;" ::: "memory");
            st_rel_cluster_u32(nxt ? rf1 : rf0, (unsigned)t);
        }
        // spin on LOCAL flags[nxt][0..7] until all == t (acquire loads)
        {
            unsigned fbase = fb + (unsigned)nxt * 32u;
            unsigned long long exp2 =
                ((unsigned long long)(unsigned)t << 32) | (unsigned)t;
            while (ld_acq_u64(fbase)      != exp2 ||
                   ld_acq_u64(fbase + 8)  != exp2 ||
                   ld_acq_u64(fbase + 16) != exp2 ||
                   ld_acq_u64(fbase + 24) != exp2) { }
        }
    }

    // final h is in hs[0] (last step wrote buffer SQ&1 == 0)
    if (rank == 0) {
        for (int idx = tid; idx < out_n; idx += 1024)
            out[idx] = hs[0][idx & (HD - 1)];
    }
}

// ---------------- launch ----------------
extern "C" void kernel_launch(void* const* d_in, const int* in_sizes, int n_in,
                              void* d_out, int out_size) {
    const int*   tokens = (const int*)d_in[0];
    const float* emb    = (const float*)d_in[1];
    const float* Wq     = (const float*)d_in[2];
    const float* bq     = (const float*)d_in[3];
    const float* Wk     = (const float*)d_in[4];
    const float* bk     = (const float*)d_in[5];
    const float* Wv     = (const float*)d_in[6];
    const float* bv     = (const float*)d_in[7];
    const float* Wo     = (const float*)d_in[8];
    const float* bo     = (const float*)d_in[9];
    const float* ln_g   = (const float*)d_in[10];
    const float* ln_b   = (const float*)d_in[11];
    const float* W_ih   = (const float*)d_in[12];
    const float* W_hh   = (const float*)d_in[13];
    const float* b_ih   = (const float*)d_in[14];
    const float* b_hh   = (const float*)d_in[15];
    float* out = (float*)d_out;

    float *px, *ps, *po, *pyo, *py, *pgi;
    __nv_bfloat16 *pqb, *pkb, *pvb, *ppb;
    cudaGetSymbolAddress((void**)&px,  g_x);
    cudaGetSymbolAddress((void**)&pqb, g_qb);
    cudaGetSymbolAddress((void**)&pkb, g_kb);
    cudaGetSymbolAddress((void**)&pvb, g_vb);
    cudaGetSymbolAddress((void**)&ps,  g_scores);
    cudaGetSymbolAddress((void**)&ppb, g_pb);
    cudaGetSymbolAddress((void**)&po,  g_ocat);
    cudaGetSymbolAddress((void**)&pyo, g_yo);
    cudaGetSymbolAddress((void**)&py,  g_y);
    cudaGetSymbolAddress((void**)&pgi, g_gi);

    const long long SH = (long long)SQ * HD;
    const long long SS = (long long)SQ * SQ;

    // 1. embed
    embed_kernel<<<SQ, HD>>>(tokens, emb);

    // 2. QKV projections (fp32 compute, bf16 output)
    dim3 gqkv(2, 32, NHEAD);
    sgemm_kernel<false, true, true><<<gqkv, 256>>>(SQ, HD, HD, px, HD, 0,
                                                   Wq, HD, (long long)HD * HD, bq, HD,
                                                   pqb, HD, SH, 1.0f);
    sgemm_kernel<false, true, true><<<gqkv, 256>>>(SQ, HD, HD, px, HD, 0,
                                                   Wk, HD, (long long)HD * HD, bk, HD,
                                                   pkb, HD, SH, 1.0f);
    sgemm_kernel<false, true, true><<<gqkv, 256>>>(SQ, HD, HD, px, HD, 0,
                                                   Wv, HD, (long long)HD * HD, bv, HD,
                                                   pvb, HD, SH, 1.0f);

    // 3. scores = q @ k^T (raw; 1/16 folded into softmax) — bf16 tensor cores
    dim3 gqk(32, 32, NHEAD);
    bf16gemm_kernel<true><<<gqk, 256>>>(SQ, SQ, HD, pqb, HD, SH,
                                        pkb, HD, SH, ps, SQ, SS);

    // 4. softmax (fp32 -> bf16 P)
    softmax_kernel<<<NHEAD * SQ, 256>>>(ps, ppb);

    // 5. o = P @ v (bf16 tensor cores) -> concat layout fp32
    dim3 gpv(2, 32, NHEAD);
    bf16gemm_kernel<false><<<gpv, 256>>>(SQ, HD, SQ, ppb, SQ, SS,
                                         pvb, HD, SH, po, NHEAD * HD, HD);

    // 6. out projection: yo = ocat @ Wo + bo (fp32)
    dim3 gproj(2, 32, 1);
    sgemm_kernel<false, true, false><<<gproj, 256>>>(SQ, HD, NHEAD * HD,
                                                     po, NHEAD * HD, 0,
                                                     Wo, HD, 0, bo, 0,
                                                     pyo, HD, 0, 1.0f);

    // 7. y = LayerNorm(x + yo)
    addln_kernel<<<SQ, 256>>>(ln_g, ln_b);

    // 8. gi = y @ W_ih^T + b_ih (fp32, NT)
    dim3 ggi(6, 32, 1);
    sgemm_kernel<true, true, false><<<ggi, 256>>>(SQ, H3, HD, py, HD, 0,
                                                  W_ih, HD, 0, b_ih, 0,
                                                  pgi, H3, 0, 1.0f);

    // 9. cluster GRU scan (flag-poll handshake)
    gru_cluster_kernel<<<8, 1024>>>(pgi, W_hh, b_hh, out, out_size);
}

// round 15
// speedup vs baseline: 1.2290x; 1.2290x over previous
#include <cuda_runtime.h>
#include <cuda_bf16.h>
#include <mma.h>

using namespace nvcuda;

#define SQ 4096
#define HD 256
#define NHEAD 6
#define H3 768

// ---------------- scratch (static __device__ — no allocation) ----------------
__device__ float g_x[SQ * HD];                            // embedded tokens
__device__ __nv_bfloat16 g_qb[NHEAD * SQ * HD];           // q (bf16)
__device__ __nv_bfloat16 g_kb[NHEAD * SQ * HD];           // k (bf16)
__device__ __nv_bfloat16 g_vb[NHEAD * SQ * HD];           // v (bf16)
__device__ float g_scores[(size_t)NHEAD * SQ * SQ];       // raw scores fp32
__device__ __nv_bfloat16 g_pb[(size_t)NHEAD * SQ * SQ];   // softmax(P) bf16
__device__ float g_ocat[SQ * NHEAD * HD];                 // concat [s][h*H+e]
__device__ float g_yo[SQ * HD];                           // attn projection out
__device__ float g_y[SQ * HD];                            // post-LN
__device__ float g_gi[SQ * H3];                           // y @ W_ih^T + b_ih

// ---------------- packed f32x2 helpers ----------------
__device__ __forceinline__ unsigned long long pack2f(float x) {
    unsigned long long r;
    asm("mov.b64 %0, {%1, %1};" : "=l"(r) : "f"(x));
    return r;
}
__device__ __forceinline__ unsigned long long pack2(float lo, float hi) {
    unsigned long long r;
    asm("mov.b64 %0, {%1, %2};" : "=l"(r) : "f"(lo), "f"(hi));
    return r;
}
__device__ __forceinline__ void unpack2(unsigned long long v, float& lo, float& hi) {
    asm("mov.b64 {%0, %1}, %2;" : "=f"(lo), "=f"(hi) : "l"(v));
}
__device__ __forceinline__ void ffma2(unsigned long long& d,
                                      unsigned long long a,
                                      unsigned long long b) {
    asm("fma.rn.f32x2 %0, %1, %2, %3;" : "=l"(d) : "l"(a), "l"(b), "l"(d));
}
__device__ __forceinline__ unsigned smem_u32(const void* p) {
    unsigned r;
    asm("{ .reg .u64 t; cvta.to.shared.u64 t, %1; cvt.u32.u64 %0, t; }"
        : "=r"(r) : "l"(p));
    return r;
}
__device__ __forceinline__ unsigned mapa_rank(unsigned addr, unsigned rank) {
    unsigned r;
    asm("mapa.shared::cluster.u32 %0, %1, %2;" : "=r"(r) : "r"(addr), "r"(rank));
    return r;
}
__device__ __forceinline__ void st_cluster_f32(unsigned addr, float v) {
    asm volatile("st.shared::cluster.f32 [%0], %1;" :: "r"(addr), "f"(v) : "memory");
}
__device__ __forceinline__ void mbar_init(unsigned addr, unsigned count) {
    asm volatile("mbarrier.init.shared.b64 [%0], %1;" :: "r"(addr), "r"(count) : "memory");
}
__device__ __forceinline__ void mbar_arrive_remote(unsigned raddr) {
    asm volatile("mbarrier.arrive.release.cluster.shared::cluster.b64 _, [%0];"
                 :: "r"(raddr) : "memory");
}
__device__ __forceinline__ void mbar_wait_cluster(unsigned addr, unsigned parity) {
    asm volatile(
        "{\n\t"
        ".reg .pred P;\n\t"
        "WL_%=:\n\t"
        "mbarrier.try_wait.parity.acquire.cluster.shared::cta.b64 P, [%0], %1, 0x989680;\n\t"
        "@P bra.uni WD_%=;\n\t"
        "bra.uni WL_%=;\n\t"
        "WD_%=:\n\t"
        "}"
        :: "r"(addr), "r"(parity) : "memory");
}
__device__ __forceinline__ unsigned my_ctarank() {
    unsigned r;
    asm("mov.u32 %0, %%cluster_ctarank;" : "=r"(r));
    return r;
}

// ---------------- embedding gather ----------------
__global__ void embed_kernel(const int* __restrict__ tok,
                             const float* __restrict__ emb) {
    int s = blockIdx.x, t = threadIdx.x;
    g_x[s * HD + t] = emb[(long long)tok[s] * HD + t];
}

// ---------------- fp32 SGEMM (f32x2 packed), optional bf16 output -----------
template <bool TRANSB, bool HASBIAS, bool OUTBF16>
__global__ __launch_bounds__(256, 2)
void sgemm_kernel(int M, int N, int K,
                  const float* __restrict__ A, int lda, long long sA,
                  const float* __restrict__ B, int ldb, long long sB,
                  const float* __restrict__ bias, int sBias,
                  void* __restrict__ Cv, int ldc, long long sC,
                  float alpha) {
    __shared__ float As[2][16][132];
    __shared__ float Bs[2][16][132];

    int z = blockIdx.z;
    A += (long long)z * sA;
    B += (long long)z * sB;
    const float* bp = HASBIAS ? (bias + (long long)z * sBias) : nullptr;

    int tid = threadIdx.x;
    int tx = tid & 15, ty = tid >> 4;
    int brow = blockIdx.y * 128, bcol = blockIdx.x * 128;

    int lrow = tid >> 1;
    int lcb  = (tid & 1) * 8;
    int bkr  = tid >> 4;
    int bcb  = (tid & 15) * 8;

    unsigned long long acc[8][4];
#pragma unroll
    for (int i = 0; i < 8; i++)
#pragma unroll
        for (int j = 0; j < 4; j++) acc[i][j] = 0ull;

    float4 na0, na1, nb0, nb1;

    auto LOADG = [&](int k0) {
        const float* ap = A + (long long)(brow + lrow) * lda + k0 + lcb;
        na0 = *(const float4*)ap;
        na1 = *(const float4*)(ap + 4);
        if (TRANSB) {
            const float* bpt = B + (long long)(bcol + lrow) * ldb + k0 + lcb;
            nb0 = *(const float4*)bpt;
            nb1 = *(const float4*)(bpt + 4);
        } else {
            const float* bpt = B + (long long)(k0 + bkr) * ldb + bcol + bcb;
            nb0 = *(const float4*)bpt;
            nb1 = *(const float4*)(bpt + 4);
        }
    };
    auto STORES = [&](int buf) {
        As[buf][lcb + 0][lrow] = na0.x; As[buf][lcb + 1][lrow] = na0.y;
        As[buf][lcb + 2][lrow] = na0.z; As[buf][lcb + 3][lrow] = na0.w;
        As[buf][lcb + 4][lrow] = na1.x; As[buf][lcb + 5][lrow] = na1.y;
        As[buf][lcb + 6][lrow] = na1.z; As[buf][lcb + 7][lrow] = na1.w;
        if (TRANSB) {
            Bs[buf][lcb + 0][lrow] = nb0.x; Bs[buf][lcb + 1][lrow] = nb0.y;
            Bs[buf][lcb + 2][lrow] = nb0.z; Bs[buf][lcb + 3][lrow] = nb0.w;
            Bs[buf][lcb + 4][lrow] = nb1.x; Bs[buf][lcb + 5][lrow] = nb1.y;
            Bs[buf][lcb + 6][lrow] = nb1.z; Bs[buf][lcb + 7][lrow] = nb1.w;
        } else {
            *(float4*)&Bs[buf][bkr][bcb]     = nb0;
            *(float4*)&Bs[buf][bkr][bcb + 4] = nb1;
        }
    };

    LOADG(0);
    STORES(0);
    __syncthreads();

    int buf = 0;
    for (int k0 = 0; k0 < K; k0 += 16) {
        bool has_next = (k0 + 16) < K;
        if (has_next) LOADG(k0 + 16);
#pragma unroll
        for (int kk = 0; kk < 16; kk++) {
            float av[8];
            *(float4*)&av[0] = *(const float4*)&As[buf][kk][ty * 8];
            *(float4*)&av[4] = *(const float4*)&As[buf][kk][ty * 8 + 4];
            unsigned long long bq[4];
            bq[0] = *(const unsigned long long*)&Bs[buf][kk][tx * 8];
            bq[1] = *(const unsigned long long*)&Bs[buf][kk][tx * 8 + 2];
            bq[2] = *(const unsigned long long*)&Bs[buf][kk][tx * 8 + 4];
            bq[3] = *(const unsigned long long*)&Bs[buf][kk][tx * 8 + 6];
#pragma unroll
            for (int i = 0; i < 8; i++) {
                unsigned long long apk = pack2f(av[i]);
                ffma2(acc[i][0], apk, bq[0]);
                ffma2(acc[i][1], apk, bq[1]);
                ffma2(acc[i][2], apk, bq[2]);
                ffma2(acc[i][3], apk, bq[3]);
            }
        }
        if (has_next) {
            STORES(buf ^ 1);
            __syncthreads();
            buf ^= 1;
        }
    }

    float bb[8];
    if (HASBIAS) {
        *(float4*)&bb[0] = *(const float4*)&bp[bcol + tx * 8];
        *(float4*)&bb[4] = *(const float4*)&bp[bcol + tx * 8 + 4];
    }
#pragma unroll
    for (int i = 0; i < 8; i++) {
        long long row = brow + ty * 8 + i;
        float2 p0, p1, p2, p3;
        unpack2(acc[i][0], p0.x, p0.y);
        unpack2(acc[i][1], p1.x, p1.y);
        unpack2(acc[i][2], p2.x, p2.y);
        unpack2(acc[i][3], p3.x, p3.y);
        float4 o0, o1;
        o0.x = p0.x * alpha; o0.y = p0.y * alpha;
        o0.z = p1.x * alpha; o0.w = p1.y * alpha;
        o1.x = p2.x * alpha; o1.y = p2.y * alpha;
        o1.z = p3.x * alpha; o1.w = p3.y * alpha;
        if (HASBIAS) {
            o0.x += bb[0]; o0.y += bb[1]; o0.z += bb[2]; o0.w += bb[3];
            o1.x += bb[4]; o1.y += bb[5]; o1.z += bb[6]; o1.w += bb[7];
        }
        long long coff = row * (long long)ldc + bcol + tx * 8 + (long long)z * sC;
        if (OUTBF16) {
            __nv_bfloat16* cb = (__nv_bfloat16*)Cv + coff;
            __nv_bfloat162 hb[4];
            hb[0] = __floats2bfloat162_rn(o0.x, o0.y);
            hb[1] = __floats2bfloat162_rn(o0.z, o0.w);
            hb[2] = __floats2bfloat162_rn(o1.x, o1.y);
            hb[3] = __floats2bfloat162_rn(o1.z, o1.w);
            *(uint4*)cb = *(uint4*)hb;
        } else {
            float* cr = (float*)Cv + coff;
            *(float4*)cr = o0;
            *(float4*)(cr + 4) = o1;
        }
    }
}

// ---------------- bf16 wmma GEMM: C(fp32) = A(bf16) * B(^T)(bf16) -----------
template <bool TRANSB>
__global__ __launch_bounds__(256, 2)
void bf16gemm_kernel(int M, int N, int K,
                     const __nv_bfloat16* __restrict__ A, int lda, long long sA,
                     const __nv_bfloat16* __restrict__ B, int ldb, long long sB,
                     float* __restrict__ C, int ldc, long long sC) {
    __shared__ __align__(16) __nv_bfloat16 As[128][40];
    __shared__ __align__(16) __nv_bfloat16 Bsh[128 * 40];   // NT: [n][40]; NN: [32][136]

    int z = blockIdx.z;
    A += (long long)z * sA;
    B += (long long)z * sB;
    C += (long long)z * sC;

    int tid = threadIdx.x;
    int wid = tid >> 5;
    int warp_m = wid & 3;
    int warp_n = wid >> 2;
    int brow = blockIdx.y * 128, bcol = blockIdx.x * 128;

    wmma::fragment<wmma::accumulator, 16, 16, 16, float> acc[2][4];
#pragma unroll
    for (int mi = 0; mi < 2; mi++)
#pragma unroll
        for (int ni = 0; ni < 4; ni++) wmma::fill_fragment(acc[mi][ni], 0.0f);

    for (int k0 = 0; k0 < K; k0 += 32) {
#pragma unroll
        for (int j = 0; j < 2; j++) {
            int u = tid + 256 * j;
            int row = u >> 2, col = (u & 3) * 8;
            const __nv_bfloat16* src = A + (long long)(brow + row) * lda + k0 + col;
            *(uint4*)&As[row][col] = *(const uint4*)src;
        }
        if (TRANSB) {
#pragma unroll
            for (int j = 0; j < 2; j++) {
                int u = tid + 256 * j;
                int row = u >> 2, col = (u & 3) * 8;
                const __nv_bfloat16* src = B + (long long)(bcol + row) * ldb + k0 + col;
                *(uint4*)&Bsh[row * 40 + col] = *(const uint4*)src;
            }
        } else {
#pragma unroll
            for (int j = 0; j < 2; j++) {
                int u = tid + 256 * j;
                int row = u >> 4, col = (u & 15) * 8;
                const __nv_bfloat16* src = B + (long long)(k0 + row) * ldb + bcol + col;
                *(uint4*)&Bsh[row * 136 + col] = *(const uint4*)src;
            }
        }
        __syncthreads();

#pragma unroll
        for (int ks = 0; ks < 2; ks++) {
            int kk = ks * 16;
            wmma::fragment<wmma::matrix_a, 16, 16, 16, __nv_bfloat16, wmma::row_major> af[2];
#pragma unroll
            for (int mi = 0; mi < 2; mi++)
                wmma::load_matrix_sync(af[mi], &As[warp_m * 32 + mi * 16][kk], 40);
            if (TRANSB) {
                wmma::fragment<wmma::matrix_b, 16, 16, 16, __nv_bfloat16, wmma::col_major> bf[4];
#pragma unroll
                for (int ni = 0; ni < 4; ni++)
                    wmma::load_matrix_sync(bf[ni], &Bsh[(warp_n * 64 + ni * 16) * 40 + kk], 40);
#pragma unroll
                for (int mi = 0; mi < 2; mi++)
#pragma unroll
                    for (int ni = 0; ni < 4; ni++)
                        wmma::mma_sync(acc[mi][ni], af[mi], bf[ni], acc[mi][ni]);
            } else {
                wmma::fragment<wmma::matrix_b, 16, 16, 16, __nv_bfloat16, wmma::row_major> bf[4];
#pragma unroll
                for (int ni = 0; ni < 4; ni++)
                    wmma::load_matrix_sync(bf[ni], &Bsh[kk * 136 + warp_n * 64 + ni * 16], 136);
#pragma unroll
                for (int mi = 0; mi < 2; mi++)
#pragma unroll
                    for (int ni = 0; ni < 4; ni++)
                        wmma::mma_sync(acc[mi][ni], af[mi], bf[ni], acc[mi][ni]);
            }
        }
        __syncthreads();
    }

#pragma unroll
    for (int mi = 0; mi < 2; mi++)
#pragma unroll
        for (int ni = 0; ni < 4; ni++) {
            long long row = brow + warp_m * 32 + mi * 16;
            long long col = bcol + warp_n * 64 + ni * 16;
            wmma::store_matrix_sync(C + row * ldc + col, acc[mi][ni], ldc,
                                    wmma::mem_row_major);
        }
}

// ---------------- row softmax (fp32 in, bf16 out), 1/16 scale folded --------
__global__ __launch_bounds__(256) void softmax_kernel(const float* __restrict__ P,
                                                      __nv_bfloat16* __restrict__ Pb) {
    __shared__ float sm[8];
    __shared__ float bc;
    long long base = (long long)blockIdx.x * SQ;
    const float4* p4 = (const float4*)(P + base);
    __nv_bfloat162* ob = (__nv_bfloat162*)(Pb + base);
    int tid = threadIdx.x;

    float4 v[4];
#pragma unroll
    for (int i = 0; i < 4; i++) v[i] = p4[tid + 256 * i];

    float m = -1e30f;
#pragma unroll
    for (int i = 0; i < 4; i++)
        m = fmaxf(m, fmaxf(fmaxf(v[i].x, v[i].y), fmaxf(v[i].z, v[i].w)));
#pragma unroll
    for (int off = 16; off; off >>= 1)
        m = fmaxf(m, __shfl_xor_sync(0xffffffffu, m, off));
    if ((tid & 31) == 0) sm[tid >> 5] = m;
    __syncthreads();
    if (tid == 0) {
        float t = sm[0];
#pragma unroll
        for (int j = 1; j < 8; j++) t = fmaxf(t, sm[j]);
        bc = t;
    }
    __syncthreads();
    m = bc;

    float s = 0.f;
#pragma unroll
    for (int i = 0; i < 4; i++) {
        v[i].x = __expf((v[i].x - m) * 0.0625f);
        v[i].y = __expf((v[i].y - m) * 0.0625f);
        v[i].z = __expf((v[i].z - m) * 0.0625f);
        v[i].w = __expf((v[i].w - m) * 0.0625f);
        s += v[i].x + v[i].y + v[i].z + v[i].w;
    }
#pragma unroll
    for (int off = 16; off; off >>= 1)
        s += __shfl_xor_sync(0xffffffffu, s, off);
    __syncthreads();
    if ((tid & 31) == 0) sm[tid >> 5] = s;
    __syncthreads();
    if (tid == 0) {
        float t = 0.f;
#pragma unroll
        for (int j = 0; j < 8; j++) t += sm[j];
        bc = 1.0f / t;
    }
    __syncthreads();
    float inv = bc;
#pragma unroll
    for (int i = 0; i < 4; i++) {
        int idx = tid + 256 * i;
        ob[idx * 2 + 0] = __floats2bfloat162_rn(v[i].x * inv, v[i].y * inv);
        ob[idx * 2 + 1] = __floats2bfloat162_rn(v[i].z * inv, v[i].w * inv);
    }
}

// ---------------- residual + LayerNorm ----------------
__global__ __launch_bounds__(256) void addln_kernel(const float* __restrict__ lng,
                                                    const float* __restrict__ lnb) {
    __shared__ float sm[8];
    __shared__ float bc;
    int s = blockIdx.x, t = threadIdx.x;
    float v = g_x[s * HD + t] + g_yo[s * HD + t];

    float a = v;
#pragma unroll
    for (int off = 16; off; off >>= 1) a += __shfl_xor_sync(0xffffffffu, a, off);
    if ((t & 31) == 0) sm[t >> 5] = a;
    __syncthreads();
    if (t == 0) {
        float tt = 0.f;
#pragma unroll
        for (int j = 0; j < 8; j++) tt += sm[j];
        bc = tt * (1.0f / HD);
    }
    __syncthreads();
    float mu = bc;
    float d = v - mu;
    float q = d * d;
    __syncthreads();
#pragma unroll
    for (int off = 16; off; off >>= 1) q += __shfl_xor_sync(0xffffffffu, q, off);
    if ((t & 31) == 0) sm[t >> 5] = q;
    __syncthreads();
    if (t == 0) {
        float tt = 0.f;
#pragma unroll
        for (int j = 0; j < 8; j++) tt += sm[j];
        bc = tt * (1.0f / HD);
    }
    __syncthreads();
    float var = bc;
    g_y[s * HD + t] = d * rsqrtf(var + 1e-5f) * lng[t] + lnb[t];
}

// ---------------- cluster GRU scan (single-waiter mbarrier handshake) -------
// 8-CTA cluster, 1024 threads each. CTA rank b owns hidden [b*32, b*32+32);
// warp w computes i = b*32 + w with 8 elems/lane of W_hh in registers.
// Per step:
//   1. lanes 0..7 of each warp store h2 into all 8 CTAs' hs[nxt] (DSMEM)
//   2. __syncthreads        — orders all warps' stores before the arrive
//   3. warp 0 lanes 0..7    — one mbarrier.arrive.release.cluster per CTA
//   4. warp 0 ONLY          — try_wait.parity.acquire.cluster spin
//   5. __syncthreads        — releases warps 1..31 (hb chains the acquire)
// Exactly R7's (correct) scheme but with ONE spinning warp instead of 32 —
// the 32-warp TRYWAIT hammering was the measured regression cause.
__global__ void __cluster_dims__(8, 1, 1) __launch_bounds__(1024, 1)
gru_cluster_kernel(const float* __restrict__ gi,
                   const float* __restrict__ Whh,
                   const float* __restrict__ bhh,
                   float* __restrict__ out, int out_n) {
    __shared__ float hs[2][HD];
    __shared__ __align__(8) unsigned long long mbar;

    int tid = threadIdx.x;
    int w = tid >> 5, l = tid & 31;
    unsigned rank = my_ctarank();
    int i = (int)rank * 32 + w;

    // register-resident, pair-packed W_hh slices
    unsigned long long wrp[4], wzp[4], wnp[4];
    {
        const float4* r4 = (const float4*)(Whh + (long long)i * HD + l * 8);
        float4 t0 = r4[0], t1 = r4[1];
        wrp[0] = pack2(t0.x, t0.y); wrp[1] = pack2(t0.z, t0.w);
        wrp[2] = pack2(t1.x, t1.y); wrp[3] = pack2(t1.z, t1.w);
        const float4* z4 = (const float4*)(Whh + (long long)(HD + i) * HD + l * 8);
        t0 = z4[0]; t1 = z4[1];
        wzp[0] = pack2(t0.x, t0.y); wzp[1] = pack2(t0.z, t0.w);
        wzp[2] = pack2(t1.x, t1.y); wzp[3] = pack2(t1.z, t1.w);
        const float4* n4 = (const float4*)(Whh + (long long)(2 * HD + i) * HD + l * 8);
        t0 = n4[0]; t1 = n4[1];
        wnp[0] = pack2(t0.x, t0.y); wnp[1] = pack2(t0.z, t0.w);
        wnp[2] = pack2(t1.x, t1.y); wnp[3] = pack2(t1.z, t1.w);
    }
    float br = 0.f, bz = 0.f, bn = 0.f;
    if (l == 0) { br = bhh[i]; bz = bhh[HD + i]; bn = bhh[2 * HD + i]; }

    unsigned hb = smem_u32(&hs[0][0]);
    unsigned mb = smem_u32(&mbar);

    // remote h-store addresses for this warp's slot (lanes 0..7 -> rank l)
    unsigned ra0 = 0, ra1 = 0;
    if (l < 8) {
        ra0 = mapa_rank(hb + (unsigned)i * 4u, (unsigned)l);
        ra1 = mapa_rank(hb + (unsigned)(HD + i) * 4u, (unsigned)l);
    }
    // remote mbar addresses (warp 0 lanes 0..7 -> rank l)
    unsigned rmb = 0;
    if (w == 0 && l < 8) rmb = mapa_rank(mb, (unsigned)l);

    if (tid < HD) { hs[0][tid] = 0.0f; hs[1][tid] = 0.0f; }
    if (tid == 0) mbar_init(mb, 8);
    __syncthreads();
    // init + zeroed hs visible cluster-wide before any arrivals/stores
    asm volatile("barrier.cluster.arrive.aligned;" ::: "memory");
    asm volatile("barrier.cluster.wait.aligned;" ::: "memory");

    const float* gp = gi + i;
    float gir = 0.f, giz = 0.f, gin = 0.f;
    if (l == 0) { gir = __ldg(gp); giz = __ldg(gp + HD); gin = __ldg(gp + 2 * HD); }
    gp += H3;

    for (int t = 0; t < SQ; t++) {
        int cur = t & 1;
        const unsigned long long* hq = (const unsigned long long*)&hs[cur][l * 8];
        unsigned long long h0 = hq[0], h1 = hq[1], h2p = hq[2], h3 = hq[3];
        unsigned long long ar = 0ull, az = 0ull, an = 0ull;
        ffma2(ar, wrp[0], h0); ffma2(az, wzp[0], h0); ffma2(an, wnp[0], h0);
        ffma2(ar, wrp[1], h1); ffma2(az, wzp[1], h1); ffma2(an, wnp[1], h1);
        ffma2(ar, wrp[2], h2p); ffma2(az, wzp[2], h2p); ffma2(an, wnp[2], h2p);
        ffma2(ar, wrp[3], h3); ffma2(az, wzp[3], h3); ffma2(an, wnp[3], h3);
        float drl, drh, dzl, dzh, dnl, dnh;
        unpack2(ar, drl, drh);
        unpack2(az, dzl, dzh);
        unpack2(an, dnl, dnh);
        float dr = drl + drh, dz = dzl + dzh, dn = dnl + dnh;
#pragma unroll
        for (int off = 16; off; off >>= 1) {
            dr += __shfl_xor_sync(0xffffffffu, dr, off);
            dz += __shfl_xor_sync(0xffffffffu, dz, off);
            dn += __shfl_xor_sync(0xffffffffu, dn, off);
        }
        float h2 = 0.f;
        if (l == 0) {
            float hprev = hs[cur][i];
            float r = 1.0f / (1.0f + __expf(-(gir + br + dr)));
            float z = 1.0f / (1.0f + __expf(-(giz + bz + dz)));
            float n = tanhf(gin + r * (dn + bn));
            h2 = (1.0f - z) * n + z * hprev;
        }
        h2 = __shfl_sync(0xffffffffu, h2, 0);
        // prefetch next step's gi (hides under bar + arrive + wait)
        if (l == 0 && t + 1 < SQ) {
            gir = __ldg(gp); giz = __ldg(gp + HD); gin = __ldg(gp + 2 * HD);
            gp += H3;
        }
        if (l < 8) {
            st_cluster_f32(((t + 1) & 1) ? ra1 : ra0, h2);
        }
        __syncthreads();                 // orders all warps' stores (cumulative)
        if (w == 0) {
            if (l < 8) mbar_arrive_remote(rmb);  // 1 arrival per src CTA per dest
            mbar_wait_cluster(mb, (unsigned)(t & 1));  // SINGLE spinning warp
        }
        __syncthreads();                 // release warps 1..31; hb chains acquire
    }

    // final h is in hs[0] (last step wrote buffer SQ&1 == 0)
    if (rank == 0) {
        for (int idx = tid; idx < out_n; idx += 1024)
            out[idx] = hs[0][idx & (HD - 1)];
    }
}

// ---------------- launch ----------------
extern "C" void kernel_launch(void* const* d_in, const int* in_sizes, int n_in,
                              void* d_out, int out_size) {
    const int*   tokens = (const int*)d_in[0];
    const float* emb    = (const float*)d_in[1];
    const float* Wq     = (const float*)d_in[2];
    const float* bq     = (const float*)d_in[3];
    const float* Wk     = (const float*)d_in[4];
    const float* bk     = (const float*)d_in[5];
    const float* Wv     = (const float*)d_in[6];
    const float* bv     = (const float*)d_in[7];
    const float* Wo     = (const float*)d_in[8];
    const float* bo     = (const float*)d_in[9];
    const float* ln_g   = (const float*)d_in[10];
    const float* ln_b   = (const float*)d_in[11];
    const float* W_ih   = (const float*)d_in[12];
    const float* W_hh   = (const float*)d_in[13];
    const float* b_ih   = (const float*)d_in[14];
    const float* b_hh   = (const float*)d_in[15];
    float* out = (float*)d_out;

    float *px, *ps, *po, *pyo, *py, *pgi;
    __nv_bfloat16 *pqb, *pkb, *pvb, *ppb;
    cudaGetSymbolAddress((void**)&px,  g_x);
    cudaGetSymbolAddress((void**)&pqb, g_qb);
    cudaGetSymbolAddress((void**)&pkb, g_kb);
    cudaGetSymbolAddress((void**)&pvb, g_vb);
    cudaGetSymbolAddress((void**)&ps,  g_scores);
    cudaGetSymbolAddress((void**)&ppb, g_pb);
    cudaGetSymbolAddress((void**)&po,  g_ocat);
    cudaGetSymbolAddress((void**)&pyo, g_yo);
    cudaGetSymbolAddress((void**)&py,  g_y);
    cudaGetSymbolAddress((void**)&pgi, g_gi);

    const long long SH = (long long)SQ * HD;
    const long long SS = (long long)SQ * SQ;

    // 1. embed
    embed_kernel<<<SQ, HD>>>(tokens, emb);

    // 2. QKV projections (fp32 compute, bf16 output)
    dim3 gqkv(2, 32, NHEAD);
    sgemm_kernel<false, true, true><<<gqkv, 256>>>(SQ, HD, HD, px, HD, 0,
                                                   Wq, HD, (long long)HD * HD, bq, HD,
                                                   pqb, HD, SH, 1.0f);
    sgemm_kernel<false, true, true><<<gqkv, 256>>>(SQ, HD, HD, px, HD, 0,
                                                   Wk, HD, (long long)HD * HD, bk, HD,
                                                   pkb, HD, SH, 1.0f);
    sgemm_kernel<false, true, true><<<gqkv, 256>>>(SQ, HD, HD, px, HD, 0,
                                                   Wv, HD, (long long)HD * HD, bv, HD,
                                                   pvb, HD, SH, 1.0f);

    // 3. scores = q @ k^T (raw; 1/16 folded into softmax) — bf16 tensor cores
    dim3 gqk(32, 32, NHEAD);
    bf16gemm_kernel<true><<<gqk, 256>>>(SQ, SQ, HD, pqb, HD, SH,
                                        pkb, HD, SH, ps, SQ, SS);

    // 4. softmax (fp32 -> bf16 P)
    softmax_kernel<<<NHEAD * SQ, 256>>>(ps, ppb);

    // 5. o = P @ v (bf16 tensor cores) -> concat layout fp32
    dim3 gpv(2, 32, NHEAD);
    bf16gemm_kernel<false><<<gpv, 256>>>(SQ, HD, SQ, ppb, SQ, SS,
                                         pvb, HD, SH, po, NHEAD * HD, HD);

    // 6. out projection: yo = ocat @ Wo + bo (fp32)
    dim3 gproj(2, 32, 1);
    sgemm_kernel<false, true, false><<<gproj, 256>>>(SQ, HD, NHEAD * HD,
                                                     po, NHEAD * HD, 0,
                                                     Wo, HD, 0, bo, 0,
                                                     pyo, HD, 0, 1.0f);

    // 7. y = LayerNorm(x + yo)
    addln_kernel<<<SQ, 256>>>(ln_g, ln_b);

    // 8. gi = y @ W_ih^T + b_ih (fp32, NT)
    dim3 ggi(6, 32, 1);
    sgemm_kernel<true, true, false><<<ggi, 256>>>(SQ, H3, HD, py, HD, 0,
                                                  W_ih, HD, 0, b_ih, 0,
                                                  pgi, H3, 0, 1.0f);

    // 9. cluster GRU scan (single-waiter mbarrier handshake)
    gru_cluster_kernel<<<8, 1024>>>(pgi, W_hh, b_hh, out, out_size);
}

// round 16
// speedup vs baseline: 1.3172x; 1.0718x over previous
#include <cuda_runtime.h>
#include <cuda_bf16.h>

#define SQ 4096
#define HD 256
#define NHEAD 6
#define H3 768

// ---------------- scratch (static __device__ — no allocation) ----------------
__device__ float g_x[SQ * HD];                            // embedded tokens
__device__ __nv_bfloat16 g_qb[NHEAD * SQ * HD];           // q (bf16)
__device__ __nv_bfloat16 g_kb[NHEAD * SQ * HD];           // k (bf16)
__device__ __nv_bfloat16 g_vb[NHEAD * SQ * HD];           // v (bf16)
__device__ float g_ocat[SQ * NHEAD * HD];                 // concat [s][h*H+e]
__device__ float g_yo[SQ * HD];                           // attn projection out
__device__ float g_y[SQ * HD];                            // post-LN
__device__ float g_gi[SQ * H3];                           // y @ W_ih^T + b_ih

// ---------------- packed f32x2 helpers ----------------
__device__ __forceinline__ unsigned long long pack2f(float x) {
    unsigned long long r;
    asm("mov.b64 %0, {%1, %1};" : "=l"(r) : "f"(x));
    return r;
}
__device__ __forceinline__ unsigned long long pack2(float lo, float hi) {
    unsigned long long r;
    asm("mov.b64 %0, {%1, %2};" : "=l"(r) : "f"(lo), "f"(hi));
    return r;
}
__device__ __forceinline__ void unpack2(unsigned long long v, float& lo, float& hi) {
    asm("mov.b64 {%0, %1}, %2;" : "=f"(lo), "=f"(hi) : "l"(v));
}
__device__ __forceinline__ void ffma2(unsigned long long& d,
                                      unsigned long long a,
                                      unsigned long long b) {
    asm("fma.rn.f32x2 %0, %1, %2, %3;" : "=l"(d) : "l"(a), "l"(b), "l"(d));
}
__device__ __forceinline__ unsigned smem_u32(const void* p) {
    unsigned r;
    asm("{ .reg .u64 t; cvta.to.shared.u64 t, %1; cvt.u32.u64 %0, t; }"
        : "=r"(r) : "l"(p));
    return r;
}
__device__ __forceinline__ unsigned mapa_rank(unsigned addr, unsigned rank) {
    unsigned r;
    asm("mapa.shared::cluster.u32 %0, %1, %2;" : "=r"(r) : "r"(addr), "r"(rank));
    return r;
}
__device__ __forceinline__ void st_cluster_f32(unsigned addr, float v) {
    asm volatile("st.shared::cluster.f32 [%0], %1;" :: "r"(addr), "f"(v) : "memory");
}
__device__ __forceinline__ unsigned my_ctarank() {
    unsigned r;
    asm("mov.u32 %0, %%cluster_ctarank;" : "=r"(r));
    return r;
}

// ---------------- mma / ldmatrix helpers (bf16, m16n8k16) --------------------
__device__ __forceinline__ void ldsm_x4(unsigned addr, unsigned& r0, unsigned& r1,
                                        unsigned& r2, unsigned& r3) {
    asm volatile("ldmatrix.sync.aligned.m8n8.x4.shared.b16 {%0,%1,%2,%3}, [%4];"
                 : "=r"(r0), "=r"(r1), "=r"(r2), "=r"(r3) : "r"(addr));
}
__device__ __forceinline__ void ldsm_x4t(unsigned addr, unsigned& r0, unsigned& r1,
                                         unsigned& r2, unsigned& r3) {
    asm volatile("ldmatrix.sync.aligned.m8n8.x4.trans.shared.b16 {%0,%1,%2,%3}, [%4];"
                 : "=r"(r0), "=r"(r1), "=r"(r2), "=r"(r3) : "r"(addr));
}
__device__ __forceinline__ void mma16816(float* c, unsigned a0, unsigned a1,
                                         unsigned a2, unsigned a3,
                                         unsigned b0, unsigned b1) {
    asm volatile(
        "mma.sync.aligned.m16n8k16.row.col.f32.bf16.bf16.f32 "
        "{%0,%1,%2,%3}, {%4,%5,%6,%7}, {%8,%9}, {%0,%1,%2,%3};"
        : "+f"(c[0]), "+f"(c[1]), "+f"(c[2]), "+f"(c[3])
        : "r"(a0), "r"(a1), "r"(a2), "r"(a3), "r"(b0), "r"(b1));
}

// ---------------- embedding gather ----------------
__global__ void embed_kernel(const int* __restrict__ tok,
                             const float* __restrict__ emb) {
    int s = blockIdx.x, t = threadIdx.x;
    g_x[s * HD + t] = emb[(long long)tok[s] * HD + t];
}

// ---------------- fp32 SGEMM (f32x2 packed), optional bf16 output -----------
template <bool TRANSB, bool HASBIAS, bool OUTBF16>
__global__ __launch_bounds__(256, 2)
void sgemm_kernel(int M, int N, int K,
                  const float* __restrict__ A, int lda, long long sA,
                  const float* __restrict__ B, int ldb, long long sB,
                  const float* __restrict__ bias, int sBias,
                  void* __restrict__ Cv, int ldc, long long sC,
                  float alpha) {
    __shared__ float As[2][16][132];
    __shared__ float Bs[2][16][132];

    int z = blockIdx.z;
    A += (long long)z * sA;
    B += (long long)z * sB;
    const float* bp = HASBIAS ? (bias + (long long)z * sBias) : nullptr;

    int tid = threadIdx.x;
    int tx = tid & 15, ty = tid >> 4;
    int brow = blockIdx.y * 128, bcol = blockIdx.x * 128;

    int lrow = tid >> 1;
    int lcb  = (tid & 1) * 8;
    int bkr  = tid >> 4;
    int bcb  = (tid & 15) * 8;

    unsigned long long acc[8][4];
#pragma unroll
    for (int i = 0; i < 8; i++)
#pragma unroll
        for (int j = 0; j < 4; j++) acc[i][j] = 0ull;

    float4 na0, na1, nb0, nb1;

    auto LOADG = [&](int k0) {
        const float* ap = A + (long long)(brow + lrow) * lda + k0 + lcb;
        na0 = *(const float4*)ap;
        na1 = *(const float4*)(ap + 4);
        if (TRANSB) {
            const float* bpt = B + (long long)(bcol + lrow) * ldb + k0 + lcb;
            nb0 = *(const float4*)bpt;
            nb1 = *(const float4*)(bpt + 4);
        } else {
            const float* bpt = B + (long long)(k0 + bkr) * ldb + bcol + bcb;
            nb0 = *(const float4*)bpt;
            nb1 = *(const float4*)(bpt + 4);
        }
    };
    auto STORES = [&](int buf) {
        As[buf][lcb + 0][lrow] = na0.x; As[buf][lcb + 1][lrow] = na0.y;
        As[buf][lcb + 2][lrow] = na0.z; As[buf][lcb + 3][lrow] = na0.w;
        As[buf][lcb + 4][lrow] = na1.x; As[buf][lcb + 5][lrow] = na1.y;
        As[buf][lcb + 6][lrow] = na1.z; As[buf][lcb + 7][lrow] = na1.w;
        if (TRANSB) {
            Bs[buf][lcb + 0][lrow] = nb0.x; Bs[buf][lcb + 1][lrow] = nb0.y;
            Bs[buf][lcb + 2][lrow] = nb0.z; Bs[buf][lcb + 3][lrow] = nb0.w;
            Bs[buf][lcb + 4][lrow] = nb1.x; Bs[buf][lcb + 5][lrow] = nb1.y;
            Bs[buf][lcb + 6][lrow] = nb1.z; Bs[buf][lcb + 7][lrow] = nb1.w;
        } else {
            *(float4*)&Bs[buf][bkr][bcb]     = nb0;
            *(float4*)&Bs[buf][bkr][bcb + 4] = nb1;
        }
    };

    LOADG(0);
    STORES(0);
    __syncthreads();

    int buf = 0;
    for (int k0 = 0; k0 < K; k0 += 16) {
        bool has_next = (k0 + 16) < K;
        if (has_next) LOADG(k0 + 16);
#pragma unroll
        for (int kk = 0; kk < 16; kk++) {
            float av[8];
            *(float4*)&av[0] = *(const float4*)&As[buf][kk][ty * 8];
            *(float4*)&av[4] = *(const float4*)&As[buf][kk][ty * 8 + 4];
            unsigned long long bq[4];
            bq[0] = *(const unsigned long long*)&Bs[buf][kk][tx * 8];
            bq[1] = *(const unsigned long long*)&Bs[buf][kk][tx * 8 + 2];
            bq[2] = *(const unsigned long long*)&Bs[buf][kk][tx * 8 + 4];
            bq[3] = *(const unsigned long long*)&Bs[buf][kk][tx * 8 + 6];
#pragma unroll
            for (int i = 0; i < 8; i++) {
                unsigned long long apk = pack2f(av[i]);
                ffma2(acc[i][0], apk, bq[0]);
                ffma2(acc[i][1], apk, bq[1]);
                ffma2(acc[i][2], apk, bq[2]);
                ffma2(acc[i][3], apk, bq[3]);
            }
        }
        if (has_next) {
            STORES(buf ^ 1);
            __syncthreads();
            buf ^= 1;
        }
    }

    float bb[8];
    if (HASBIAS) {
        *(float4*)&bb[0] = *(const float4*)&bp[bcol + tx * 8];
        *(float4*)&bb[4] = *(const float4*)&bp[bcol + tx * 8 + 4];
    }
#pragma unroll
    for (int i = 0; i < 8; i++) {
        long long row = brow + ty * 8 + i;
        float2 p0, p1, p2, p3;
        unpack2(acc[i][0], p0.x, p0.y);
        unpack2(acc[i][1], p1.x, p1.y);
        unpack2(acc[i][2], p2.x, p2.y);
        unpack2(acc[i][3], p3.x, p3.y);
        float4 o0, o1;
        o0.x = p0.x * alpha; o0.y = p0.y * alpha;
        o0.z = p1.x * alpha; o0.w = p1.y * alpha;
        o1.x = p2.x * alpha; o1.y = p2.y * alpha;
        o1.z = p3.x * alpha; o1.w = p3.y * alpha;
        if (HASBIAS) {
            o0.x += bb[0]; o0.y += bb[1]; o0.z += bb[2]; o0.w += bb[3];
            o1.x += bb[4]; o1.y += bb[5]; o1.z += bb[6]; o1.w += bb[7];
        }
        long long coff = row * (long long)ldc + bcol + tx * 8 + (long long)z * sC;
        if (OUTBF16) {
            __nv_bfloat16* cb = (__nv_bfloat16*)Cv + coff;
            __nv_bfloat162 hb[4];
            hb[0] = __floats2bfloat162_rn(o0.x, o0.y);
            hb[1] = __floats2bfloat162_rn(o0.z, o0.w);
            hb[2] = __floats2bfloat162_rn(o1.x, o1.y);
            hb[3] = __floats2bfloat162_rn(o1.z, o1.w);
            *(uint4*)cb = *(uint4*)hb;
        } else {
            float* cr = (float*)Cv + coff;
            *(float4*)cr = o0;
            *(float4*)(cr + 4) = o1;
        }
    }
}

// ---------------- fused flash attention ----------------
// Grid (SQ/64, NHEAD), 256 threads (8 warps: warp_m=wid&3 -> 16 Q rows,
// warp_n=wid>>2 -> 128 O cols / 32 S keys). KV tiles of 64.
// Online softmax with 1/16 scale folded into exp. O accum in registers
// (m16n8 fp32 frags, known row layout for per-row alpha rescale).
#define QKV_STRIDE 264          // 256 + 8 bf16 pad
#define SS_STRIDE  68           // 64 + 4 fp32 pad
#define PS_STRIDE  72           // 64 + 8 bf16 pad
#define FLASH_SMEM (3 * 64 * QKV_STRIDE * 2 + 64 * SS_STRIDE * 4 + 64 * PS_STRIDE * 2 + 3 * 64 * 4)

__global__ __launch_bounds__(256, 1)
void flash_kernel(const __nv_bfloat16* __restrict__ Qg,
                  const __nv_bfloat16* __restrict__ Kg,
                  const __nv_bfloat16* __restrict__ Vg,
                  float* __restrict__ Og) {
    extern __shared__ char smraw[];
    __nv_bfloat16* Qs = (__nv_bfloat16*)smraw;              // 64 x QKV_STRIDE
    __nv_bfloat16* Ks = Qs + 64 * QKV_STRIDE;
    __nv_bfloat16* Vs = Ks + 64 * QKV_STRIDE;
    float* Ssm = (float*)(Vs + 64 * QKV_STRIDE);            // 64 x SS_STRIDE
    __nv_bfloat16* Psm = (__nv_bfloat16*)(Ssm + 64 * SS_STRIDE); // 64 x PS_STRIDE
    float* mrow = (float*)(Psm + 64 * PS_STRIDE);
    float* lrow = mrow + 64;
    float* arow = lrow + 64;

    int head = blockIdx.y;
    int q0 = blockIdx.x * 64;
    const __nv_bfloat16* Qh = Qg + (long long)head * SQ * HD;
    const __nv_bfloat16* Kh = Kg + (long long)head * SQ * HD;
    const __nv_bfloat16* Vh = Vg + (long long)head * SQ * HD;

    int tid = threadIdx.x;
    int lane = tid & 31;
    int wid = tid >> 5;
    int warp_m = wid & 3;       // 16-row chunk of Q
    int warp_n = wid >> 2;      // 0/1

    // load Q tile (64 x 256 bf16)
    for (int idx = tid; idx < 64 * 32; idx += 256) {
        int r = idx >> 5, c = (idx & 31) * 8;
        *(uint4*)&Qs[r * QKV_STRIDE + c] = *(const uint4*)&Qh[(long long)(q0 + r) * HD + c];
    }
    if (tid < 64) { mrow[tid] = -1e30f; lrow[tid] = 0.0f; }

    float oa[16][4];
#pragma unroll
    for (int i = 0; i < 16; i++)
#pragma unroll
        for (int j = 0; j < 4; j++) oa[i][j] = 0.0f;

    // precomputed per-lane ldmatrix coordinates
    int a_r = warp_m * 16 + (lane & 15);              // A-frag row (Q / P)
    int a_c8 = (lane >> 4) * 8;                       // A-frag col offset
    int sb_n = (lane & 7) + ((lane & 16) ? 8 : 0);    // S-B n offset
    int sb_k = (lane & 8) ? 8 : 0;                    // S-B k offset
    int vb_k = lane & 15;                             // V-B k offset (trans)
    int vb_n8 = (lane & 16) ? 8 : 0;                  // V-B n offset
    int c_r = warp_m * 16 + (lane >> 2);              // accum row
    int c_c = (lane & 3) * 2;                         // accum col pair

    int sm_r = tid >> 2;                              // softmax row
    int sm_c = (tid & 3) * 16;                        // softmax col base

    for (int kt = 0; kt < 64; kt++) {
        __syncthreads();   // protect Ks/Vs/Psm from prior iteration's readers
        int key0 = kt * 64;
        for (int idx = tid; idx < 64 * 32; idx += 256) {
            int r = idx >> 5, c = (idx & 31) * 8;
            *(uint4*)&Ks[r * QKV_STRIDE + c] = *(const uint4*)&Kh[(long long)(key0 + r) * HD + c];
            *(uint4*)&Vs[r * QKV_STRIDE + c] = *(const uint4*)&Vh[(long long)(key0 + r) * HD + c];
        }
        __syncthreads();

        // ---- S = Q K^T (warp: 16 rows x 32 keys, 4 n-frags) ----
        float sa[4][4];
#pragma unroll
        for (int f = 0; f < 4; f++)
#pragma unroll
            for (int j = 0; j < 4; j++) sa[f][j] = 0.0f;

#pragma unroll
        for (int ks = 0; ks < 16; ks++) {
            unsigned a0, a1, a2, a3;
            ldsm_x4(smem_u32(&Qs[a_r * QKV_STRIDE + ks * 16 + a_c8]), a0, a1, a2, a3);
            unsigned b0, b1, b2, b3;
            ldsm_x4(smem_u32(&Ks[(warp_n * 32 + sb_n) * QKV_STRIDE + ks * 16 + sb_k]),
                    b0, b1, b2, b3);
            mma16816(sa[0], a0, a1, a2, a3, b0, b1);
            mma16816(sa[1], a0, a1, a2, a3, b2, b3);
            ldsm_x4(smem_u32(&Ks[(warp_n * 32 + 16 + sb_n) * QKV_STRIDE + ks * 16 + sb_k]),
                    b0, b1, b2, b3);
            mma16816(sa[2], a0, a1, a2, a3, b0, b1);
            mma16816(sa[3], a0, a1, a2, a3, b2, b3);
        }
        // store S frags to smem
#pragma unroll
        for (int f = 0; f < 4; f++) {
            int c = warp_n * 32 + f * 8 + c_c;
            *(float2*)&Ssm[c_r * SS_STRIDE + c] = make_float2(sa[f][0], sa[f][1]);
            *(float2*)&Ssm[(c_r + 8) * SS_STRIDE + c] = make_float2(sa[f][2], sa[f][3]);
        }
        __syncthreads();

        // ---- online softmax update (4 threads per row, 16 cols each) ----
        {
            float v[16];
            *(float4*)&v[0]  = *(const float4*)&Ssm[sm_r * SS_STRIDE + sm_c];
            *(float4*)&v[4]  = *(const float4*)&Ssm[sm_r * SS_STRIDE + sm_c + 4];
            *(float4*)&v[8]  = *(const float4*)&Ssm[sm_r * SS_STRIDE + sm_c + 8];
            *(float4*)&v[12] = *(const float4*)&Ssm[sm_r * SS_STRIDE + sm_c + 12];
            float mt = v[0];
#pragma unroll
            for (int j = 1; j < 16; j++) mt = fmaxf(mt, v[j]);
            mt = fmaxf(mt, __shfl_xor_sync(0xffffffffu, mt, 1));
            mt = fmaxf(mt, __shfl_xor_sync(0xffffffffu, mt, 2));
            float mo = mrow[sm_r];
            float mn = fmaxf(mo, mt);
            float al = __expf((mo - mn) * 0.0625f);
            float s = 0.0f;
            __nv_bfloat162 pb[8];
#pragma unroll
            for (int j = 0; j < 8; j++) {
                float p0 = __expf((v[2 * j]     - mn) * 0.0625f);
                float p1 = __expf((v[2 * j + 1] - mn) * 0.0625f);
                s += p0 + p1;
                pb[j] = __floats2bfloat162_rn(p0, p1);
            }
            s += __shfl_xor_sync(0xffffffffu, s, 1);
            s += __shfl_xor_sync(0xffffffffu, s, 2);
            *(uint4*)&Psm[sm_r * PS_STRIDE + sm_c]     = *(uint4*)&pb[0];
            *(uint4*)&Psm[sm_r * PS_STRIDE + sm_c + 8] = *(uint4*)&pb[4];
            if ((tid & 3) == 0) {
                mrow[sm_r] = mn;
                lrow[sm_r] = lrow[sm_r] * al + s;
                arow[sm_r] = al;
            }
        }
        __syncthreads();

        // ---- rescale O, then O += P V ----
        {
            float al0 = arow[c_r];
            float al1 = arow[c_r + 8];
#pragma unroll
            for (int f = 0; f < 16; f++) {
                oa[f][0] *= al0; oa[f][1] *= al0;
                oa[f][2] *= al1; oa[f][3] *= al1;
            }
#pragma unroll
            for (int kk = 0; kk < 4; kk++) {
                unsigned a0, a1, a2, a3;
                ldsm_x4(smem_u32(&Psm[a_r * PS_STRIDE + kk * 16 + a_c8]), a0, a1, a2, a3);
#pragma unroll
                for (int j = 0; j < 8; j++) {
                    int nb = warp_n * 128 + j * 16;
                    unsigned b0, b1, b2, b3;
                    ldsm_x4t(smem_u32(&Vs[(kk * 16 + vb_k) * QKV_STRIDE + nb + vb_n8]),
                             b0, b1, b2, b3);
                    mma16816(oa[2 * j],     a0, a1, a2, a3, b0, b1);
                    mma16816(oa[2 * j + 1], a0, a1, a2, a3, b2, b3);
                }
            }
        }
    }

    // ---- epilogue: O / l -> g_ocat concat layout ----
    float inv0 = 1.0f / lrow[c_r];
    float inv1 = 1.0f / lrow[c_r + 8];
    long long rowbase0 = (long long)(q0 + c_r) * (NHEAD * HD) + head * HD;
    long long rowbase1 = (long long)(q0 + c_r + 8) * (NHEAD * HD) + head * HD;
#pragma unroll
    for (int f = 0; f < 16; f++) {
        int c = warp_n * 128 + f * 8 + c_c;
        *(float2*)&Og[rowbase0 + c] = make_float2(oa[f][0] * inv0, oa[f][1] * inv0);
        *(float2*)&Og[rowbase1 + c] = make_float2(oa[f][2] * inv1, oa[f][3] * inv1);
    }
}

// ---------------- residual + LayerNorm ----------------
__global__ __launch_bounds__(256) void addln_kernel(const float* __restrict__ lng,
                                                    const float* __restrict__ lnb) {
    __shared__ float sm[8];
    __shared__ float bc;
    int s = blockIdx.x, t = threadIdx.x;
    float v = g_x[s * HD + t] + g_yo[s * HD + t];

    float a = v;
#pragma unroll
    for (int off = 16; off; off >>= 1) a += __shfl_xor_sync(0xffffffffu, a, off);
    if ((t & 31) == 0) sm[t >> 5] = a;
    __syncthreads();
    if (t == 0) {
        float tt = 0.f;
#pragma unroll
        for (int j = 0; j < 8; j++) tt += sm[j];
        bc = tt * (1.0f / HD);
    }
    __syncthreads();
    float mu = bc;
    float d = v - mu;
    float q = d * d;
    __syncthreads();
#pragma unroll
    for (int off = 16; off; off >>= 1) q += __shfl_xor_sync(0xffffffffu, q, off);
    if ((t & 31) == 0) sm[t >> 5] = q;
    __syncthreads();
    if (t == 0) {
        float tt = 0.f;
#pragma unroll
        for (int j = 0; j < 8; j++) tt += sm[j];
        bc = tt * (1.0f / HD);
    }
    __syncthreads();
    float var = bc;
    g_y[s * HD + t] = d * rsqrtf(var + 1e-5f) * lng[t] + lnb[t];
}

// ---------------- cluster GRU scan (R4 measured-best: barrier.cluster) ------
__global__ void __cluster_dims__(8, 1, 1) __launch_bounds__(1024, 1)
gru_cluster_kernel(const float* __restrict__ gi,
                   const float* __restrict__ Whh,
                   const float* __restrict__ bhh,
                   float* __restrict__ out, int out_n) {
    __shared__ float hs[2][HD];
    int tid = threadIdx.x;
    int w = tid >> 5, l = tid & 31;
    unsigned rank = my_ctarank();
    int i = (int)rank * 32 + w;

    // register-resident, pair-packed W_hh slices
    unsigned long long wrp[4], wzp[4], wnp[4];
    {
        const float4* r4 = (const float4*)(Whh + (long long)i * HD + l * 8);
        float4 t0 = r4[0], t1 = r4[1];
        wrp[0] = pack2(t0.x, t0.y); wrp[1] = pack2(t0.z, t0.w);
        wrp[2] = pack2(t1.x, t1.y); wrp[3] = pack2(t1.z, t1.w);
        const float4* z4 = (const float4*)(Whh + (long long)(HD + i) * HD + l * 8);
        t0 = z4[0]; t1 = z4[1];
        wzp[0] = pack2(t0.x, t0.y); wzp[1] = pack2(t0.z, t0.w);
        wzp[2] = pack2(t1.x, t1.y); wzp[3] = pack2(t1.z, t1.w);
        const float4* n4 = (const float4*)(Whh + (long long)(2 * HD + i) * HD + l * 8);
        t0 = n4[0]; t1 = n4[1];
        wnp[0] = pack2(t0.x, t0.y); wnp[1] = pack2(t0.z, t0.w);
        wnp[2] = pack2(t1.x, t1.y); wnp[3] = pack2(t1.z, t1.w);
    }
    float br = 0.f, bz = 0.f, bn = 0.f;
    if (l == 0) { br = bhh[i]; bz = bhh[HD + i]; bn = bhh[2 * HD + i]; }

    // remote store addresses for this warp's h slot (lanes 0..7 -> rank l)
    unsigned hb = smem_u32(&hs[0][0]);
    unsigned ra0 = 0, ra1 = 0;
    if (l < 8) {
        ra0 = mapa_rank(hb + (unsigned)i * 4u, (unsigned)l);
        ra1 = mapa_rank(hb + (unsigned)(HD + i) * 4u, (unsigned)l);
    }

    if (tid < HD) { hs[0][tid] = 0.0f; hs[1][tid] = 0.0f; }
    asm volatile("barrier.cluster.arrive.aligned;" ::: "memory");
    asm volatile("barrier.cluster.wait.aligned;" ::: "memory");

    const float* gp = gi + i;
    float gir = 0.f, giz = 0.f, gin = 0.f;
    if (l == 0) { gir = __ldg(gp); giz = __ldg(gp + HD); gin = __ldg(gp + 2 * HD); }
    gp += H3;

    for (int t = 0; t < SQ; t++) {
        int cur = t & 1;
        const unsigned long long* hq = (const unsigned long long*)&hs[cur][l * 8];
        unsigned long long h0 = hq[0], h1 = hq[1], h2p = hq[2], h3 = hq[3];
        unsigned long long ar = 0ull, az = 0ull, an = 0ull;
        ffma2(ar, wrp[0], h0); ffma2(az, wzp[0], h0); ffma2(an, wnp[0], h0);
        ffma2(ar, wrp[1], h1); ffma2(az, wzp[1], h1); ffma2(an, wnp[1], h1);
        ffma2(ar, wrp[2], h2p); ffma2(az, wzp[2], h2p); ffma2(an, wnp[2], h2p);
        ffma2(ar, wrp[3], h3); ffma2(az, wzp[3], h3); ffma2(an, wnp[3], h3);
        float drl, drh, dzl, dzh, dnl, dnh;
        unpack2(ar, drl, drh);
        unpack2(az, dzl, dzh);
        unpack2(an, dnl, dnh);
        float dr = drl + drh, dz = dzl + dzh, dn = dnl + dnh;
#pragma unroll
        for (int off = 16; off; off >>= 1) {
            dr += __shfl_xor_sync(0xffffffffu, dr, off);
            dz += __shfl_xor_sync(0xffffffffu, dz, off);
            dn += __shfl_xor_sync(0xffffffffu, dn, off);
        }
        float h2 = 0.f;
        if (l == 0) {
            float hprev = hs[cur][i];
            float r = 1.0f / (1.0f + __expf(-(gir + br + dr)));
            float z = 1.0f / (1.0f + __expf(-(giz + bz + dz)));
            float n = tanhf(gin + r * (dn + bn));
            h2 = (1.0f - z) * n + z * hprev;
        }
        h2 = __shfl_sync(0xffffffffu, h2, 0);
        if (l == 0 && t + 1 < SQ) {
            gir = __ldg(gp); giz = __ldg(gp + HD); gin = __ldg(gp + 2 * HD);
            gp += H3;
        }
        if (l < 8) {
            st_cluster_f32(((t + 1) & 1) ? ra1 : ra0, h2);
        }
        asm volatile("barrier.cluster.arrive.aligned;" ::: "memory");
        asm volatile("barrier.cluster.wait.aligned;" ::: "memory");
    }

    if (rank == 0) {
        for (int idx = tid; idx < out_n; idx += 1024)
            out[idx] = hs[0][idx & (HD - 1)];
    }
}

// ---------------- launch ----------------
extern "C" void kernel_launch(void* const* d_in, const int* in_sizes, int n_in,
                              void* d_out, int out_size) {
    const int*   tokens = (const int*)d_in[0];
    const float* emb    = (const float*)d_in[1];
    const float* Wq     = (const float*)d_in[2];
    const float* bq     = (const float*)d_in[3];
    const float* Wk     = (const float*)d_in[4];
    const float* bk     = (const float*)d_in[5];
    const float* Wv     = (const float*)d_in[6];
    const float* bv     = (const float*)d_in[7];
    const float* Wo     = (const float*)d_in[8];
    const float* bo     = (const float*)d_in[9];
    const float* ln_g   = (const float*)d_in[10];
    const float* ln_b   = (const float*)d_in[11];
    const float* W_ih   = (const float*)d_in[12];
    const float* W_hh   = (const float*)d_in[13];
    const float* b_ih   = (const float*)d_in[14];
    const float* b_hh   = (const float*)d_in[15];
    float* out = (float*)d_out;

    float *px, *po, *pyo, *py, *pgi;
    __nv_bfloat16 *pqb, *pkb, *pvb;
    cudaGetSymbolAddress((void**)&px,  g_x);
    cudaGetSymbolAddress((void**)&pqb, g_qb);
    cudaGetSymbolAddress((void**)&pkb, g_kb);
    cudaGetSymbolAddress((void**)&pvb, g_vb);
    cudaGetSymbolAddress((void**)&po,  g_ocat);
    cudaGetSymbolAddress((void**)&pyo, g_yo);
    cudaGetSymbolAddress((void**)&py,  g_y);
    cudaGetSymbolAddress((void**)&pgi, g_gi);

    const long long SH = (long long)SQ * HD;

    // opt-in large dynamic smem for flash (idempotent; no allocation)
    cudaFuncSetAttribute(flash_kernel,
                         cudaFuncAttributeMaxDynamicSharedMemorySize, FLASH_SMEM);

    // 1. embed
    embed_kernel<<<SQ, HD>>>(tokens, emb);

    // 2. QKV projections (fp32 compute, bf16 output)
    dim3 gqkv(2, 32, NHEAD);
    sgemm_kernel<false, true, true><<<gqkv, 256>>>(SQ, HD, HD, px, HD, 0,
                                                   Wq, HD, (long long)HD * HD, bq, HD,
                                                   pqb, HD, SH, 1.0f);
    sgemm_kernel<false, true, true><<<gqkv, 256>>>(SQ, HD, HD, px, HD, 0,
                                                   Wk, HD, (long long)HD * HD, bk, HD,
                                                   pkb, HD, SH, 1.0f);
    sgemm_kernel<false, true, true><<<gqkv, 256>>>(SQ, HD, HD, px, HD, 0,
                                                   Wv, HD, (long long)HD * HD, bv, HD,
                                                   pvb, HD, SH, 1.0f);

    // 3-5. fused flash attention -> concat layout fp32
    flash_kernel<<<dim3(SQ / 64, NHEAD), 256, FLASH_SMEM>>>(pqb, pkb, pvb, po);

    // 6. out projection: yo = ocat @ Wo + bo (fp32)
    dim3 gproj(2, 32, 1);
    sgemm_kernel<false, true, false><<<gproj, 256>>>(SQ, HD, NHEAD * HD,
                                                     po, NHEAD * HD, 0,
                                                     Wo, HD, 0, bo, 0,
                                                     pyo, HD, 0, 1.0f);

    // 7. y = LayerNorm(x + yo)
    addln_kernel<<<SQ, 256>>>(ln_g, ln_b);

    // 8. gi = y @ W_ih^T + b_ih (fp32, NT)
    dim3 ggi(6, 32, 1);
    sgemm_kernel<true, true, false><<<ggi, 256>>>(SQ, H3, HD, py, HD, 0,
                                                  W_ih, HD, 0, b_ih, 0,
                                                  pgi, H3, 0, 1.0f);

    // 9. cluster GRU scan (measured-best R4 barrier.cluster handshake)
    gru_cluster_kernel<<<8, 1024>>>(pgi, W_hh, b_hh, out, out_size);
}